// round 16
// baseline (speedup 1.0000x reference)
#include <cuda_runtime.h>
#include <cuda_fp16.h>
#include <stdint.h>
#include <math.h>

// LocalRNN: B=16, L=1024, D=256, ksize=16
#define B_   16
#define L_   1024
#define D_   256
#define KS_  16
#define G_   768
#define NCH_ (B_ * L_)

// Static device scratch
__device__ float    g_gi[(size_t)NCH_ * G_];   // gi[chain][gate_dim] fp32 (50MB)
__device__ uint32_t g_wh[98304];               // W_hh fp16, rnn 4Nx4M fragment order
__device__ uint32_t g_wih[98304];              // W_ih fp16, gi B-fragment order
__device__ uint4    g_xh[524288];              // x fp16, gi A-fragment order (8MB)

__device__ __forceinline__ float tanha(float x) {
    float y; asm("tanh.approx.f32 %0, %1;" : "=f"(y) : "f"(x)); return y;
}
__device__ __forceinline__ float fsig(float x) { return fmaf(0.5f, tanha(0.5f * x), 0.5f); }
// paired-word permutation (rnn H layout)
__device__ __forceinline__ int permw(int w) {
    return (w & ~7) | ((w & 3) << 1) | ((w >> 2) & 1);
}
__device__ __forceinline__ int hword(int d) { return permw(d >> 1); }

__device__ __forceinline__ void mma16f(float* d, const uint32_t* a, uint32_t b0, uint32_t b1) {
    asm volatile(
        "mma.sync.aligned.m16n8k16.row.col.f32.f16.f16.f32 "
        "{%0,%1,%2,%3}, {%4,%5,%6,%7}, {%8,%9}, {%0,%1,%2,%3};"
        : "+f"(d[0]), "+f"(d[1]), "+f"(d[2]), "+f"(d[3])
        : "r"(a[0]), "r"(a[1]), "r"(a[2]), "r"(a[3]), "r"(b0), "r"(b1));
}

// ---------------------------------------------------------------------------
// Merged prep. W_hh rnn layout (4N x 4M tiling):
//   slab = c*4+kq (6144 words). block = ncol4*4 + k16m (384 words):
//     word = g*128 + lane*4 + o;  nt = o>>1, r = o&1
//   maps to W_hh[g*256 + c*64 + ncol4*16 + nt*8 + (lane>>2)]
//               [kq*64 + k16m*16 + 2*(lane&3) + r*8]
// ---------------------------------------------------------------------------
__global__ void prep_kernel(const float* __restrict__ x,
                            const float* __restrict__ Wih,
                            const float* __restrict__ Whh)
{
    int e = blockIdx.x * 256 + threadIdx.x;
    if (e < 98304) {
        int slab = e / 6144, w6 = e % 6144;
        int c = slab >> 2, kq = slab & 3;
        int block = w6 / 384, rem = w6 % 384;
        int g = rem >> 7;
        int rr = rem & 127;
        int lane = rr >> 2, o = rr & 3;
        int nt = o >> 1, r = o & 1;
        int ncol4 = block >> 2, k16m = block & 3;
        int k   = kq * 64 + k16m * 16 + 2 * (lane & 3) + r * 8;
        int dim = c * 64 + ncol4 * 16 + nt * 8 + (lane >> 2);
        const float* wr = Whh + (size_t)(g * 256 + dim) * D_ + k;
        __half2 h2 = __floats2half2_rn(wr[0], wr[1]);
        g_wh[e] = *(uint32_t*)&h2;
    } else if (e < 196608) {
        // W_ih -> gi B-fragment order
        int e2 = e - 98304;
        int r = e2 & 1, lane = (e2 >> 1) & 31;
        int nt = (e2 >> 6) & 7, ncol = (e2 >> 9) & 1;
        int k16 = (e2 >> 10) & 15, ntile = e2 >> 14;
        int qrow = lane >> 2, qcol = lane & 3;
        int gd = ntile * 128 + ncol * 64 + nt * 8 + qrow;
        int k  = k16 * 16 + 2 * qcol + r * 8;
        const float* wr = Wih + (size_t)gd * D_ + k;
        __half2 h2 = __floats2half2_rn(wr[0], wr[1]);
        g_wih[e2] = *(uint32_t*)&h2;
    } else {
        // x -> A-fragment image
        int e3 = e - 196608;
        if (e3 >= 524288) return;
        int lane = e3 & 31, mgroup = (e3 >> 5) & 7;
        int k16 = (e3 >> 8) & 15, cb = e3 >> 12;
        int qrow = lane >> 2, qcol = lane & 3;
        int r0 = cb * 128 + mgroup * 16 + qrow, r1 = r0 + 8;
        int kb = k16 * 16 + 2 * qcol;
        const float* x0 = x + (size_t)r0 * D_ + kb;
        const float* x1 = x + (size_t)r1 * D_ + kb;
        __half2 w0 = __floats2half2_rn(x0[0], x0[1]);
        __half2 w1 = __floats2half2_rn(x1[0], x1[1]);
        __half2 w2 = __floats2half2_rn(x0[8], x0[9]);
        __half2 w3 = __floats2half2_rn(x1[8], x1[9]);
        uint4 v;
        v.x = *(uint32_t*)&w0; v.y = *(uint32_t*)&w1;
        v.z = *(uint32_t*)&w2; v.w = *(uint32_t*)&w3;
        g_xh[e3] = v;
    }
}

// ---------------------------------------------------------------------------
// gi = x @ W_ih^T + b_ih via fp16 mma -> fp32 out (R14 proven). grid (128, 6).
// ---------------------------------------------------------------------------
#define GI_WS_W 16384
#define GI_SMEM_BYTES (GI_WS_W * 4)      // 65536 B

__global__ __launch_bounds__(256) void gi_mma_kernel(
    const float* __restrict__ bih)
{
    extern __shared__ uint32_t Wst[];

    const int tid = threadIdx.x;
    const int lane = tid & 31, wid = tid >> 5;
    const int qrow = lane >> 2, qcol = lane & 3;
    const int mwarp = wid & 3;
    const int ncol  = wid >> 2;
    const int cb = blockIdx.x;
    const int ntile = blockIdx.y;

    {   // stage Wih tile: pure linear copy from fragment image
        const uint4* ws = ((const uint4*)g_wih) + ntile * 4096;
        uint4* wd = (uint4*)Wst;
#pragma unroll
        for (int j = 0; j < 16; j++) wd[tid + j * 256] = ws[tid + j * 256];
    }
    __syncthreads();

    float acc[2][8][4];
#pragma unroll
    for (int mt = 0; mt < 2; mt++)
#pragma unroll
        for (int nt = 0; nt < 8; nt++)
#pragma unroll
            for (int e = 0; e < 4; e++) acc[mt][nt][e] = 0.f;

    const uint4* xp = g_xh + (size_t)cb * 4096;
    uint4 apf[2];
    apf[0] = xp[(mwarp * 2 + 0) * 32 + lane];
    apf[1] = xp[(mwarp * 2 + 1) * 32 + lane];

#pragma unroll
    for (int k16 = 0; k16 < 16; k16++) {
        uint4 a0 = apf[0], a1 = apf[1];
        if (k16 < 15) {
            apf[0] = xp[((k16 + 1) * 8 + mwarp * 2 + 0) * 32 + lane];
            apf[1] = xp[((k16 + 1) * 8 + mwarp * 2 + 1) * 32 + lane];
        }
        const uint32_t* wb = Wst + k16 * 1024 + ncol * 512 + lane * 2;
#pragma unroll
        for (int nt = 0; nt < 8; nt++) {
            uint2 b = *(const uint2*)(wb + nt * 64);
            mma16f(acc[0][nt], (const uint32_t*)&a0, b.x, b.y);
            mma16f(acc[1][nt], (const uint32_t*)&a1, b.x, b.y);
        }
    }

#pragma unroll
    for (int nt = 0; nt < 8; nt++) {
        const int gd = ntile * 128 + ncol * 64 + nt * 8 + 2 * qcol;
        const float2 bv = *(const float2*)(bih + gd);
#pragma unroll
        for (int mt = 0; mt < 2; mt++)
#pragma unroll
            for (int eh = 0; eh < 2; eh++) {
                const int chain = cb * 128 + mwarp * 32 + mt * 16 + eh * 8 + qrow;
                float2 o;
                o.x = acc[mt][nt][eh * 2 + 0] + bv.x;
                o.y = acc[mt][nt][eh * 2 + 1] + bv.y;
                *(float2*)(g_gi + (size_t)chain * G_ + gd) = o;
            }
    }
}

// ---------------------------------------------------------------------------
// Main recurrence, fp16 m16n8k16, 512 threads, 16 warps as 4M(x32 rows) x 4N
// (x16 dims/gate): B smem redundancy 8x -> 4x (224KB -> 160KB per kq phase).
// Double-buffered H; R14 fp32 epilogue numerics.
// ---------------------------------------------------------------------------
#define HW_S   136
#define HBUF_W (128 * HW_S)             // 17408
#define WSLAB  6144
#define SMF_WS  (2 * HBUF_W)            // 34816
#define SMF_BIH (SMF_WS + 2 * WSLAB)    // 47104
#define SMF_BHH (SMF_BIH + G_)
#define RNN_SMEM_BYTES ((SMF_BHH + G_) * 4)   // 194560 B

__global__ __launch_bounds__(512, 1) void rnn_mma_kernel(
    const float* __restrict__ bih_g,
    const float* __restrict__ bhh_g,
    float* __restrict__ out)
{
    extern __shared__ uint32_t sm[];
    uint32_t* Ws_u  = sm + SMF_WS;
    float*    bih_s = (float*)(sm + SMF_BIH);
    float*    bhh_s = (float*)(sm + SMF_BHH);

    const int tid = threadIdx.x;
    const int lane = tid & 31, wid = tid >> 5;
    const int qrow = lane >> 2, qcol = lane & 3;
    const int mbase = (wid & 3) * 32;   // 32 rows per M-warp (mt=2)
    const int ncol4 = wid >> 2;         // 16 dims/gate per N-group
    const int n0 = blockIdx.x * 128;

    for (int i = tid * 4; i < HBUF_W; i += 2048)
        *(uint4*)(sm + i) = make_uint4(0, 0, 0, 0);
    for (int i = tid; i < G_; i += 512) { bih_s[i] = bih_g[i]; bhh_s[i] = bhh_g[i]; }

    uint4 pf[3];
    {   // slab0 -> buf0, prefetch slab1
        const uint4* s = (const uint4*)g_wh;
#pragma unroll
        for (int j = 0; j < 3; j++) pf[j] = s[tid + j * 512];
        uint4* d = (uint4*)Ws_u;
#pragma unroll
        for (int j = 0; j < 3; j++) d[tid + j * 512] = pf[j];
#pragma unroll
        for (int j = 0; j < 3; j++) pf[j] = s[1536 + tid + j * 512];
    }
    __syncthreads();

    int sc = 0;   // slab phase counter (slab = sc & 15)

    for (int t = 0; t < KS_; t++) {
        uint32_t* Hcur = sm + (t & 1) * HBUF_W;
        uint32_t* Hnxt = sm + ((t + 1) & 1) * HBUF_W;

        for (int c = 0; c < 4; c++) {
            float acc[3][2][2][4];   // [gate][mt][nt][quad]
#pragma unroll
            for (int g = 0; g < 3; g++)
#pragma unroll
                for (int mt = 0; mt < 2; mt++)
#pragma unroll
                    for (int nt = 0; nt < 2; nt++)
#pragma unroll
                        for (int e = 0; e < 4; e++) acc[g][mt][nt][e] = 0.f;

            for (int kq = 0; kq < 4; kq++) {
                const uint32_t* W = Ws_u + (sc & 1) * WSLAB;
                {   // commit next slab (regs -> other buffer), overlaps MMA
                    uint4* d = (uint4*)(Ws_u + ((sc + 1) & 1) * WSLAB);
#pragma unroll
                    for (int j = 0; j < 3; j++) d[tid + j * 512] = pf[j];
                }
                {   // prefetch slab sc+2
                    const uint4* s = ((const uint4*)g_wh)
                                   + (size_t)((sc + 2) & 15) * (WSLAB / 4);
#pragma unroll
                    for (int j = 0; j < 3; j++) pf[j] = s[tid + j * 512];
                }

#pragma unroll
                for (int k16m = 0; k16m < 4; k16m++) {
                    const int k16 = kq * 4 + k16m;
                    const int ko  = k16 * 8 + 2 * qcol;
                    uint32_t a[2][4];
#pragma unroll
                    for (int mt = 0; mt < 2; mt++) {
                        const int r = mbase + mt * 16 + qrow;
                        uint2 lo = *(const uint2*)(Hcur + r * HW_S + ko);
                        uint2 hi = *(const uint2*)(Hcur + (r + 8) * HW_S + ko);
                        a[mt][0] = lo.x; a[mt][1] = hi.x;
                        a[mt][2] = lo.y; a[mt][3] = hi.y;
                    }
                    const uint32_t* wk = W + (ncol4 * 4 + k16m) * 384 + lane * 4;
#pragma unroll
                    for (int g = 0; g < 3; g++) {
                        uint4 bv = *(const uint4*)(wk + g * 128);
                        mma16f(acc[g][0][0], a[0], bv.x, bv.y);
                        mma16f(acc[g][1][0], a[1], bv.x, bv.y);
                        mma16f(acc[g][0][1], a[0], bv.z, bv.w);
                        mma16f(acc[g][1][1], a[1], bv.z, bv.w);
                    }
                }
                __syncthreads();
                sc++;
            }

            // ---- fused GRU epilogue for chunk c (16 dims/gate per warp) ----
#pragma unroll
            for (int nt = 0; nt < 2; nt++) {
                const int dwg = c * 64 + ncol4 * 16 + nt * 8 + 2 * qcol;
                const float2 bhr = *(const float2*)(bhh_s + dwg);
                const float2 bhz = *(const float2*)(bhh_s + 256 + dwg);
                const float2 bhn = *(const float2*)(bhh_s + 512 + dwg);
                const int hw = hword(dwg);
#pragma unroll
                for (int mt = 0; mt < 2; mt++)
#pragma unroll
                    for (int eh = 0; eh < 2; eh++) {
                        const int row   = mbase + mt * 16 + eh * 8 + qrow;
                        const int chain = n0 + row;
                        const int lp    = (chain & (L_ - 1)) - (KS_ - 1) + t;
                        float2 gr, gz, gn;
                        if (lp >= 0) {
                            const float* gp = g_gi + (size_t)(chain - (KS_ - 1) + t) * G_;
                            gr = *(const float2*)(gp + dwg);
                            gz = *(const float2*)(gp + 256 + dwg);
                            gn = *(const float2*)(gp + 512 + dwg);
                        } else {
                            gr = *(const float2*)(bih_s + dwg);
                            gz = *(const float2*)(bih_s + 256 + dwg);
                            gn = *(const float2*)(bih_s + 512 + dwg);
                        }
                        const __half2 hh = *(const __half2*)(Hcur + row * HW_S + hw);
                        const float2 hof = __half22float2(hh);
                        float2 hv;
#pragma unroll
                        for (int e2 = 0; e2 < 2; e2++) {
                            const float ghr = acc[0][mt][nt][eh * 2 + e2] + (e2 ? bhr.y : bhr.x);
                            const float ghz = acc[1][mt][nt][eh * 2 + e2] + (e2 ? bhz.y : bhz.x);
                            const float ghn = acc[2][mt][nt][eh * 2 + e2] + (e2 ? bhn.y : bhn.x);
                            const float rg = fsig((e2 ? gr.y : gr.x) + ghr);
                            const float zg = fsig((e2 ? gz.y : gz.x) + ghz);
                            const float ng = tanha((e2 ? gn.y : gn.x) + rg * ghn);
                            const float ho = e2 ? hof.y : hof.x;
                            (e2 ? hv.y : hv.x) = (1.f - zg) * ng + zg * ho;
                        }
                        if (t == KS_ - 1) {
                            *(float2*)(out + (size_t)chain * D_ + dwg) = hv;
                        } else {
                            __half2 hx = __floats2half2_rn(hv.x, hv.y);
                            Hnxt[row * HW_S + hw] = *(uint32_t*)&hx;
                        }
                    }
            }
        }

        if (t < KS_ - 1) __syncthreads();   // Hnxt complete before next step reads
    }
}

// ---------------------------------------------------------------------------
// Launch: prep -> gi -> rnn
// ---------------------------------------------------------------------------
extern "C" void kernel_launch(void* const* d_in, const int* in_sizes, int n_in,
                              void* d_out, int out_size)
{
    const float* x   = (const float*)d_in[0];
    const float* Wih = (const float*)d_in[1];
    const float* Whh = (const float*)d_in[2];
    const float* bih = (const float*)d_in[3];
    const float* bhh = (const float*)d_in[4];
    float* out = (float*)d_out;

    prep_kernel<<<2816, 256>>>(x, Wih, Whh);

    cudaFuncSetAttribute(gi_mma_kernel,
                         cudaFuncAttributeMaxDynamicSharedMemorySize, GI_SMEM_BYTES);
    dim3 gi_grid(NCH_ / 128, G_ / 128);
    gi_mma_kernel<<<gi_grid, 256, GI_SMEM_BYTES>>>(bih);

    cudaFuncSetAttribute(rnn_mma_kernel,
                         cudaFuncAttributeMaxDynamicSharedMemorySize, RNN_SMEM_BYTES);
    rnn_mma_kernel<<<128, 512, RNN_SMEM_BYTES>>>(bih, bhh, out);
}